// round 7
// baseline (speedup 1.0000x reference)
#include <cuda_runtime.h>
#include <cuda_fp16.h>
#include <cstdint>

// 3-kernel chain:
// 1) convert_w : Wd,Wu fp32 -> half scratch
// 2) A' fused  : per 64-token CTA: out = x+res^T (fp32 shortcut);
//                then k-loop: re-read out chunk from L2, normalize -> half smem,
//                MMA vs streamed Wd; hd = relu(.+bd) -> g_hd.   (no g_H!)
// 3) gemm2     : out = shortcut + hd @ Wu^T + bup (unchanged, proven)

#define NTOK 32768
#define DDIM 1024
#define BN   128
#define THREADS 256

__device__ __align__(16) __half g_hd[(size_t)NTOK * BN];
__device__ __align__(16) __half g_Wd[BN * DDIM];
__device__ __align__(16) __half g_Wu[DDIM * BN];

__device__ __forceinline__ void mma16(float* c, const uint32_t* a, const uint32_t* b) {
    asm volatile(
        "mma.sync.aligned.m16n8k16.row.col.f32.f16.f16.f32 "
        "{%0,%1,%2,%3}, {%4,%5,%6,%7}, {%8,%9}, {%0,%1,%2,%3};\n"
        : "+f"(c[0]), "+f"(c[1]), "+f"(c[2]), "+f"(c[3])
        : "r"(a[0]), "r"(a[1]), "r"(a[2]), "r"(a[3]), "r"(b[0]), "r"(b[1]));
}

__device__ __forceinline__ void ldsm4(uint32_t* r, const __half* p) {
    uint32_t a = (uint32_t)__cvta_generic_to_shared(p);
    asm volatile("ldmatrix.sync.aligned.m8n8.x4.shared.b16 {%0,%1,%2,%3}, [%4];\n"
                 : "=r"(r[0]), "=r"(r[1]), "=r"(r[2]), "=r"(r[3]) : "r"(a));
}

__device__ __forceinline__ void cp16(void* dst_sm, const void* src) {
    uint32_t a = (uint32_t)__cvta_generic_to_shared(dst_sm);
    asm volatile("cp.async.cg.shared.global [%0], [%1], 16;\n" :: "r"(a), "l"(src));
}
__device__ __forceinline__ void cp_commit() {
    asm volatile("cp.async.commit_group;\n");
}
template <int N>
__device__ __forceinline__ void cp_wait() {
    asm volatile("cp.async.wait_group %0;\n" :: "n"(N));
}

// ------------------------------------------------------------------ kernel 1
__global__ void convert_w(const float* __restrict__ Wd, const float* __restrict__ Wu) {
    const int i = blockIdx.x * blockDim.x + threadIdx.x; // 131072 threads
    g_Wd[i] = __float2half_rn(Wd[i]);
    g_Wu[i] = __float2half_rn(Wu[i]);
}

// ------------------------------------------------------------------ kernel A'
// smem layout (bytes):
//   smu[64]f, srs[64]f, sbd[128]f, sgam[1024]f, sbet[1024]f
//   sout 2 x [64][68]f   (fp32 chunk re-read)
//   sWd  2 x [128][72]h
//   sH   2 x [64][72]h   (normalized half chunk)
static constexpr int OFF_MU   = 0;
static constexpr int OFF_RS   = 256;
static constexpr int OFF_ABD  = 512;
static constexpr int OFF_GAM  = 1024;
static constexpr int OFF_BET  = 5120;
static constexpr int OFF_SOUT = 9216;
static constexpr int SOUT_ST  = 68;                         // floats
static constexpr int SOUT_STG = 64 * SOUT_ST;
static constexpr int OFF_SWD  = OFF_SOUT + 2 * SOUT_STG * 4;  // 43776... (9216+34816)
static constexpr int WD_ST    = 72;                         // halves
static constexpr int WD_STG   = 128 * WD_ST;
static constexpr int OFF_SH   = OFF_SWD + 2 * WD_STG * 2;
static constexpr int H_ST     = 72;                         // halves
static constexpr int H_STG    = 64 * H_ST;
static constexpr int A_SMEM   = OFF_SH + 2 * H_STG * 2;     // ~99.3KB

__global__ __launch_bounds__(THREADS, 2) void residln_gemm1(
    const float* __restrict__ x, const float* __restrict__ res,
    const float* __restrict__ gamma, const float* __restrict__ beta,
    const float* __restrict__ bd, float* __restrict__ out)
{
    extern __shared__ char smem[];
    float*  smu  = (float*)(smem + OFF_MU);
    float*  srs  = (float*)(smem + OFF_RS);
    float*  sbd  = (float*)(smem + OFF_ABD);
    float*  sgam = (float*)(smem + OFF_GAM);
    float*  sbet = (float*)(smem + OFF_BET);
    float*  soutb = (float*)(smem + OFF_SOUT);
    __half* sWdb  = (__half*)(smem + OFF_SWD);
    __half* sHb   = (__half*)(smem + OFF_SH);

    const int tid  = threadIdx.x;
    const int lane = tid & 31, warp = tid >> 5;
    const int t0   = blockIdx.x * 64;

    // ---------------- phase 0: v = x + res^T -> out; LN stats -> smem --------
    for (int i = tid; i < 1024; i += THREADS) {
        sgam[i] = gamma[i];
        sbet[i] = beta[i];
    }
    if (tid < 128) sbd[tid] = bd[tid];

    #pragma unroll 1
    for (int tt = 0; tt < 8; ++tt) {
        const int row = warp * 8 + tt;
        const int n = t0 + row;
        const int s = n >> 3, b = n & 7;
        const float4* xr = (const float4*)(x + (size_t)n * DDIM);
        const float4* rr = (const float4*)(res + ((size_t)b * 4096 + s) * DDIM);
        float4* orow = (float4*)(out + (size_t)n * DDIM);

        float sum = 0.f, sq = 0.f;
        #pragma unroll
        for (int i = 0; i < 8; ++i) {
            const int k = i * 32 + lane;
            const float4 a = xr[k], r = rr[k];
            float4 t;
            t.x = a.x + r.x; t.y = a.y + r.y; t.z = a.z + r.z; t.w = a.w + r.w;
            orow[k] = t;
            sum += t.x + t.y + t.z + t.w;
            sq  += t.x * t.x + t.y * t.y + t.z * t.z + t.w * t.w;
        }
        #pragma unroll
        for (int o = 16; o > 0; o >>= 1) {
            sum += __shfl_xor_sync(0xffffffffu, sum, o);
            sq  += __shfl_xor_sync(0xffffffffu, sq, o);
        }
        if (lane == 0) {
            const float mu  = sum * (1.f / 1024.f);
            const float var = sq * (1.f / 1024.f) - mu * mu;
            smu[row] = mu;
            srs[row] = rsqrtf(var + 1e-5f);
        }
    }
    __syncthreads();   // out writes + stats visible to whole CTA

    // ---------------- phase 1: k-loop, re-read out (L2), normalize, MMA ------
    auto issue = [&](int st, int kc) {
        const int kg0 = kc * 64;
        float* so = soutb + st * SOUT_STG;
        #pragma unroll
        for (int p = 0; p < 4; ++p) {           // out chunk: 64 x 64 fp32
            const int idx = p * THREADS + tid;
            const int row = idx >> 4, j = (idx & 15) * 4;
            cp16(so + row * SOUT_ST + j, out + (size_t)(t0 + row) * DDIM + kg0 + j);
        }
        __half* sw = sWdb + st * WD_STG;
        #pragma unroll
        for (int p = 0; p < 4; ++p) {           // Wd chunk: 128 x 64 halves
            const int idx = p * THREADS + tid;
            const int nn = idx >> 3, j = (idx & 7) * 8;
            cp16(sw + nn * WD_ST + j, g_Wd + (size_t)nn * DDIM + kg0 + j);
        }
        cp_commit();
    };

    const int mw = warp >> 2, nw = warp & 3;
    const int gid = lane >> 2, tig = lane & 3;
    const int a_row = (lane & 7) + ((lane >> 3) & 1) * 8;
    const int a_kof = (lane >> 4) * 8;
    const int b_row = (lane & 7) + (lane >> 4) * 8;
    const int b_kof = ((lane >> 3) & 1) * 8;

    float acc[2][4][4];
    #pragma unroll
    for (int i = 0; i < 2; ++i)
        #pragma unroll
        for (int j = 0; j < 4; ++j)
            #pragma unroll
            for (int q = 0; q < 4; ++q) acc[i][j][q] = 0.f;

    issue(0, 0);
    issue(1, 1);

    #pragma unroll 1
    for (int kc = 0; kc < 16; ++kc) {
        if (kc == 15) cp_wait<0>(); else cp_wait<1>();
        __syncthreads();
        const int st = kc & 1;
        const float*  so = soutb + st * SOUT_STG;
        __half*       sh = sHb + st * H_STG;
        const __half* sw = sWdb + st * WD_STG;

        // normalize fp32 chunk -> half tile
        #pragma unroll
        for (int p = 0; p < 4; ++p) {
            const int idx = p * THREADS + tid;
            const int row = idx >> 4, j = (idx & 15) * 4;
            const float4 v = *(const float4*)(so + row * SOUT_ST + j);
            const float m = smu[row], r = srs[row];
            const int kg = kc * 64 + j;
            __half2 h0 = __floats2half2_rn((v.x - m) * r * sgam[kg]     + sbet[kg],
                                           (v.y - m) * r * sgam[kg + 1] + sbet[kg + 1]);
            __half2 h1 = __floats2half2_rn((v.z - m) * r * sgam[kg + 2] + sbet[kg + 2],
                                           (v.w - m) * r * sgam[kg + 3] + sbet[kg + 3]);
            uint2 u;
            u.x = *(uint32_t*)&h0;
            u.y = *(uint32_t*)&h1;
            *(uint2*)(sh + row * H_ST + j) = u;
        }
        __syncthreads();

        #pragma unroll
        for (int ks = 0; ks < 4; ++ks) {
            const int kb0 = ks * 16;
            uint32_t a[2][4], bf[2][4];
            #pragma unroll
            for (int mt = 0; mt < 2; ++mt)
                ldsm4(a[mt], sh + (mw * 32 + mt * 16 + a_row) * H_ST + kb0 + a_kof);
            #pragma unroll
            for (int nt2 = 0; nt2 < 2; ++nt2)
                ldsm4(bf[nt2], sw + (nw * 32 + nt2 * 16 + b_row) * WD_ST + kb0 + b_kof);
            #pragma unroll
            for (int mt = 0; mt < 2; ++mt)
                #pragma unroll
                for (int nt = 0; nt < 4; ++nt)
                    mma16(acc[mt][nt], a[mt], bf[nt >> 1] + (nt & 1) * 2);
        }
        __syncthreads();
        if (kc + 2 < 16) issue((kc + 2) & 1, kc + 2);
    }

    // epilogue: +bd, relu -> g_hd
    #pragma unroll
    for (int mt = 0; mt < 2; ++mt) {
        #pragma unroll
        for (int nt = 0; nt < 4; ++nt) {
            const int row = mw * 32 + mt * 16 + gid;
            const int col = nw * 32 + nt * 8 + 2 * tig;
            const float b0 = sbd[col], b1 = sbd[col + 1];
            const float* c = acc[mt][nt];
            const size_t o = (size_t)(t0 + row) * BN + col;
            __half2 h0 = __floats2half2_rn(fmaxf(c[0] + b0, 0.f), fmaxf(c[1] + b1, 0.f));
            __half2 h1 = __floats2half2_rn(fmaxf(c[2] + b0, 0.f), fmaxf(c[3] + b1, 0.f));
            *(uint32_t*)(g_hd + o)          = *(uint32_t*)&h0;
            *(uint32_t*)(g_hd + o + 8 * BN) = *(uint32_t*)&h1;
        }
    }
}

// ------------------------------------------------------------------ kernel B
// CTA: 64 tokens x 128 out-cols; K=128; shortcut prefetched via cp.async.
static constexpr int G2_ST    = 136;
static constexpr int G2_A     = 64 * G2_ST;
static constexpr int G2_HB    = (64 + 128) * G2_ST;    // halves
static constexpr int G2_OUT   = 64 * 132;              // floats
static constexpr int G2_SMEM  = G2_HB * 2 + (G2_OUT + 128) * 4; // 86528 B

__global__ __launch_bounds__(256, 2) void gemm2(
    const float* __restrict__ bup, float* __restrict__ out)
{
    extern __shared__ __half smC[];
    __half* shd = smC;
    __half* swu = smC + G2_A;
    float*  sout = (float*)(smC + G2_HB);
    float*  sbup = sout + G2_OUT;
    const int tid  = threadIdx.x;
    const int lane = tid & 31, warp = tid >> 5;
    const int t0 = blockIdx.x * 64;
    const int nc = blockIdx.y;

    const int mw = warp >> 2, nw = warp & 3;
    const int gid = lane >> 2, tig = lane & 3;

    const int a_row = (lane & 7) + ((lane >> 3) & 1) * 8;
    const int a_kof = (lane >> 4) * 8;
    const int b_row = (lane & 7) + (lane >> 4) * 8;
    const int b_kof = ((lane >> 3) & 1) * 8;

    #pragma unroll
    for (int hk = 0; hk < 2; ++hk) {
        const int k0 = hk * 64;
        #pragma unroll
        for (int p = 0; p < 2; ++p) {           // hd: 64 x 64 halves
            const int idx = p * 256 + tid;
            const int row = idx >> 3, j = (idx & 7) * 8;
            cp16(shd + row * G2_ST + k0 + j, g_hd + (size_t)(t0 + row) * BN + k0 + j);
        }
        #pragma unroll
        for (int p = 0; p < 4; ++p) {           // Wu: 128 x 64 halves
            const int idx = p * 256 + tid;
            const int nn = idx >> 3, j = (idx & 7) * 8;
            cp16(swu + nn * G2_ST + k0 + j,
                 g_Wu + (size_t)(nc * 128 + nn) * BN + k0 + j);
        }
        cp_commit();
    }
    #pragma unroll
    for (int p = 0; p < 8; ++p) {               // shortcut: 64 x 128 floats
        const int idx = p * 256 + tid;
        const int row = idx >> 5, j = (idx & 31) * 4;
        cp16(sout + row * 132 + j, out + (size_t)(t0 + row) * DDIM + nc * 128 + j);
    }
    if (tid < 32) cp16(sbup + tid * 4, bup + nc * 128 + tid * 4);
    cp_commit();

    float acc[2][4][4];
    #pragma unroll
    for (int i = 0; i < 2; ++i)
        #pragma unroll
        for (int j = 0; j < 4; ++j)
            #pragma unroll
            for (int q = 0; q < 4; ++q) acc[i][j][q] = 0.f;

    #pragma unroll
    for (int hk = 0; hk < 2; ++hk) {
        if (hk == 0) cp_wait<2>(); else cp_wait<1>();
        __syncthreads();
        #pragma unroll
        for (int ks = 0; ks < 4; ++ks) {
            const int kb0 = hk * 64 + ks * 16;
            uint32_t a[2][4], bf[2][4];
            #pragma unroll
            for (int mt = 0; mt < 2; ++mt)
                ldsm4(a[mt], shd + (mw * 32 + mt * 16 + a_row) * G2_ST + kb0 + a_kof);
            #pragma unroll
            for (int nt2 = 0; nt2 < 2; ++nt2)
                ldsm4(bf[nt2], swu + (nw * 32 + nt2 * 16 + b_row) * G2_ST + kb0 + b_kof);
            #pragma unroll
            for (int mt = 0; mt < 2; ++mt)
                #pragma unroll
                for (int nt = 0; nt < 4; ++nt)
                    mma16(acc[mt][nt], a[mt], bf[nt >> 1] + (nt & 1) * 2);
        }
    }

    cp_wait<0>();
    __syncthreads();

    #pragma unroll
    for (int mt = 0; mt < 2; ++mt) {
        #pragma unroll
        for (int nt = 0; nt < 4; ++nt) {
            const int row  = mw * 32 + mt * 16 + gid;
            const int col  = nw * 32 + nt * 8 + 2 * tig;
            const int gcol = nc * 128 + col;
            const float b0 = sbup[col], b1 = sbup[col + 1];
            const size_t off  = (size_t)(t0 + row) * DDIM + gcol;
            const size_t off2 = off + (size_t)8 * DDIM;
            const float* c = acc[mt][nt];
            const float2 s0 = *(const float2*)(sout + row * 132 + col);
            const float2 s1 = *(const float2*)(sout + (row + 8) * 132 + col);
            float2 o0, o1;
            o0.x = c[0] + b0 + s0.x; o0.y = c[1] + b1 + s0.y;
            o1.x = c[2] + b0 + s1.x; o1.y = c[3] + b1 + s1.y;
            *(float2*)(out + off)  = o0;
            *(float2*)(out + off2) = o1;
        }
    }
}

// ------------------------------------------------------------------ launch
extern "C" void kernel_launch(void* const* d_in, const int* in_sizes, int n_in,
                              void* d_out, int out_size) {
    const float* x     = (const float*)d_in[0];
    const float* res   = (const float*)d_in[1];
    const float* gamma = (const float*)d_in[2];
    const float* beta  = (const float*)d_in[3];
    const float* Wd    = (const float*)d_in[4];
    const float* bd    = (const float*)d_in[5];
    const float* Wu    = (const float*)d_in[6];
    const float* bup   = (const float*)d_in[7];
    float* out = (float*)d_out;

    static bool attr_done = false;
    if (!attr_done) {
        cudaFuncSetAttribute(residln_gemm1,
                             cudaFuncAttributeMaxDynamicSharedMemorySize, A_SMEM);
        cudaFuncSetAttribute(gemm2,
                             cudaFuncAttributeMaxDynamicSharedMemorySize, G2_SMEM);
        attr_done = true;
    }

    convert_w<<<512, 256>>>(Wd, Wu);
    residln_gemm1<<<512, THREADS, A_SMEM>>>(x, res, gamma, beta, bd, out);
    gemm2<<<dim3(512, 8), 256, G2_SMEM>>>(bup, out);
}

// round 8
// speedup vs baseline: 1.0952x; 1.0952x over previous
#include <cuda_runtime.h>
#include <cuda_fp16.h>
#include <cstdint>

// Round-4 proven structure + gemm2 grid-swap for L2 sharing of shortcut reads.
// 1) convert_w: Wd,Wu -> half scratch (vectorized)
// 2) resid_ln : out = x + res^T (shortcut, fp32); H = half(LN(out)) -> scratch
// 3) gemm1    : hd = half(relu(H @ Wd^T + bd))  (cp.async 2-stage, LDSM)
// 4) gemm2    : out += hd @ Wu^T + bup          (LDSM, shortcut prefetched,
//               grid (8,512): col chunk fastest -> 8 CTAs share shortcut in L2)

#define NTOK 32768
#define DDIM 1024
#define BN   128

__device__ __align__(16) __half g_H [(size_t)NTOK * DDIM];
__device__ __align__(16) __half g_hd[(size_t)NTOK * BN];
__device__ __align__(16) __half g_Wd[BN * DDIM];
__device__ __align__(16) __half g_Wu[DDIM * BN];

__device__ __forceinline__ void mma16(float* c, const uint32_t* a, const uint32_t* b) {
    asm volatile(
        "mma.sync.aligned.m16n8k16.row.col.f32.f16.f16.f32 "
        "{%0,%1,%2,%3}, {%4,%5,%6,%7}, {%8,%9}, {%0,%1,%2,%3};\n"
        : "+f"(c[0]), "+f"(c[1]), "+f"(c[2]), "+f"(c[3])
        : "r"(a[0]), "r"(a[1]), "r"(a[2]), "r"(a[3]), "r"(b[0]), "r"(b[1]));
}

__device__ __forceinline__ void ldsm4(uint32_t* r, const __half* p) {
    uint32_t a = (uint32_t)__cvta_generic_to_shared(p);
    asm volatile("ldmatrix.sync.aligned.m8n8.x4.shared.b16 {%0,%1,%2,%3}, [%4];\n"
                 : "=r"(r[0]), "=r"(r[1]), "=r"(r[2]), "=r"(r[3]) : "r"(a));
}

__device__ __forceinline__ void cp16(void* dst_sm, const void* src) {
    uint32_t a = (uint32_t)__cvta_generic_to_shared(dst_sm);
    asm volatile("cp.async.cg.shared.global [%0], [%1], 16;\n" :: "r"(a), "l"(src));
}
__device__ __forceinline__ void cp_commit() {
    asm volatile("cp.async.commit_group;\n");
}
template <int N>
__device__ __forceinline__ void cp_wait() {
    asm volatile("cp.async.wait_group %0;\n" :: "n"(N));
}

// ------------------------------------------------------------------ kernel 1
__global__ void convert_w(const float* __restrict__ Wd, const float* __restrict__ Wu) {
    const int i = (blockIdx.x * 256 + threadIdx.x) * 4; // 128 blocks
    const float4 a = *(const float4*)(Wd + i);
    const float4 b = *(const float4*)(Wu + i);
    __half2 a0 = __floats2half2_rn(a.x, a.y), a1 = __floats2half2_rn(a.z, a.w);
    __half2 b0 = __floats2half2_rn(b.x, b.y), b1 = __floats2half2_rn(b.z, b.w);
    uint2 ua, ub;
    ua.x = *(uint32_t*)&a0; ua.y = *(uint32_t*)&a1;
    ub.x = *(uint32_t*)&b0; ub.y = *(uint32_t*)&b1;
    *(uint2*)(g_Wd + i) = ua;
    *(uint2*)(g_Wu + i) = ub;
}

// ------------------------------------------------------------------ kernel 2
__global__ __launch_bounds__(256) void resid_ln(
    const float* __restrict__ x, const float* __restrict__ res,
    const float* __restrict__ gamma, const float* __restrict__ beta,
    float* __restrict__ out)
{
    const int warp = threadIdx.x >> 5, lane = threadIdx.x & 31;
    const int n = blockIdx.x * 8 + warp;           // 4096 blocks
    const int s = n >> 3, b = n & 7;
    const float4* xr = (const float4*)(x + (size_t)n * DDIM);
    const float4* rr = (const float4*)(res + ((size_t)b * 4096 + s) * DDIM);
    float4* orow = (float4*)(out + (size_t)n * DDIM);
    uint2*  hrow = (uint2*)(g_H + (size_t)n * DDIM);
    const float4* g4 = (const float4*)gamma;
    const float4* b4 = (const float4*)beta;

    float4 v[8];
    float sum = 0.f, sq = 0.f;
    #pragma unroll
    for (int i = 0; i < 8; ++i) {
        const int k = i * 32 + lane;
        const float4 a = xr[k], r = rr[k];
        float4 t;
        t.x = a.x + r.x; t.y = a.y + r.y; t.z = a.z + r.z; t.w = a.w + r.w;
        v[i] = t;
        orow[k] = t;
        sum += t.x + t.y + t.z + t.w;
        sq  += t.x * t.x + t.y * t.y + t.z * t.z + t.w * t.w;
    }
    #pragma unroll
    for (int o = 16; o > 0; o >>= 1) {
        sum += __shfl_xor_sync(0xffffffffu, sum, o);
        sq  += __shfl_xor_sync(0xffffffffu, sq, o);
    }
    const float mu   = sum * (1.f / 1024.f);
    const float var  = sq * (1.f / 1024.f) - mu * mu;
    const float rstd = rsqrtf(var + 1e-5f);

    #pragma unroll
    for (int i = 0; i < 8; ++i) {
        const int k = i * 32 + lane;
        const float4 g = g4[k], be = b4[k];
        __half2 h0 = __floats2half2_rn((v[i].x - mu) * rstd * g.x + be.x,
                                       (v[i].y - mu) * rstd * g.y + be.y);
        __half2 h1 = __floats2half2_rn((v[i].z - mu) * rstd * g.z + be.z,
                                       (v[i].w - mu) * rstd * g.w + be.w);
        uint2 u;
        u.x = *(uint32_t*)&h0;
        u.y = *(uint32_t*)&h1;
        hrow[k] = u;
    }
}

// ------------------------------------------------------------------ kernel 3
// CTA: 64 tokens x 128(BN). K chunks of 64 halves, 2-stage cp.async pipeline.
static constexpr int G1_AST  = 72;                     // row stride (halves)
static constexpr int G1_STG  = (64 + 128) * G1_AST;    // halves per stage
static constexpr int G1_SMEM = 2 * G1_STG * 2;         // 55296 B

__global__ __launch_bounds__(256, 3) void gemm1(const float* __restrict__ bd)
{
    extern __shared__ __half smB[];
    const int tid  = threadIdx.x;
    const int lane = tid & 31, warp = tid >> 5;
    const int t0   = blockIdx.x * 64;

    const int mw = warp >> 2, nw = warp & 3;
    const int gid = lane >> 2, tig = lane & 3;

    const int a_row = (lane & 7) + ((lane >> 3) & 1) * 8;
    const int a_kof = (lane >> 4) * 8;
    const int b_row = (lane & 7) + (lane >> 4) * 8;
    const int b_kof = ((lane >> 3) & 1) * 8;

    auto issue = [&](int st, int kc) {
        __half* s = smB + st * G1_STG;
        const int kg0 = kc * 64;
        #pragma unroll
        for (int p = 0; p < 2; ++p) {           // A: 64 x 64 halves
            const int idx = p * 256 + tid;
            const int row = idx >> 3, j = (idx & 7) * 8;
            cp16(s + row * G1_AST + j, g_H + (size_t)(t0 + row) * DDIM + kg0 + j);
        }
        #pragma unroll
        for (int p = 0; p < 4; ++p) {           // B: 128 x 64 halves
            const int idx = p * 256 + tid;
            const int nn = idx >> 3, j = (idx & 7) * 8;
            cp16(s + 64 * G1_AST + nn * G1_AST + j, g_Wd + (size_t)nn * DDIM + kg0 + j);
        }
        cp_commit();
    };

    float acc[2][4][4];
    #pragma unroll
    for (int i = 0; i < 2; ++i)
        #pragma unroll
        for (int j = 0; j < 4; ++j)
            #pragma unroll
            for (int q = 0; q < 4; ++q) acc[i][j][q] = 0.f;

    issue(0, 0);
    issue(1, 1);

    #pragma unroll 1
    for (int kc = 0; kc < 16; ++kc) {
        if (kc == 15) cp_wait<0>(); else cp_wait<1>();
        __syncthreads();
        const __half* sa = smB + (kc & 1) * G1_STG;
        const __half* sb = sa + 64 * G1_AST;
        #pragma unroll
        for (int ks = 0; ks < 4; ++ks) {        // 4 x k16 = 64
            const int kb0 = ks * 16;
            uint32_t a[2][4], bf[2][4];
            #pragma unroll
            for (int mt = 0; mt < 2; ++mt)
                ldsm4(a[mt], sa + (mw * 32 + mt * 16 + a_row) * G1_AST + kb0 + a_kof);
            #pragma unroll
            for (int nt2 = 0; nt2 < 2; ++nt2)
                ldsm4(bf[nt2], sb + (nw * 32 + nt2 * 16 + b_row) * G1_AST + kb0 + b_kof);
            #pragma unroll
            for (int mt = 0; mt < 2; ++mt)
                #pragma unroll
                for (int nt = 0; nt < 4; ++nt)
                    mma16(acc[mt][nt], a[mt], bf[nt >> 1] + (nt & 1) * 2);
        }
        __syncthreads();
        if (kc + 2 < 16) issue((kc + 2) & 1, kc + 2);
    }

    // epilogue: +bd, relu, half -> g_hd
    #pragma unroll
    for (int mt = 0; mt < 2; ++mt) {
        #pragma unroll
        for (int nt = 0; nt < 4; ++nt) {
            const int row = mw * 32 + mt * 16 + gid;
            const int col = nw * 32 + nt * 8 + 2 * tig;
            const float b0 = bd[col], b1 = bd[col + 1];
            const float* c = acc[mt][nt];
            const size_t o = (size_t)(t0 + row) * BN + col;
            __half2 h0 = __floats2half2_rn(fmaxf(c[0] + b0, 0.f), fmaxf(c[1] + b1, 0.f));
            __half2 h1 = __floats2half2_rn(fmaxf(c[2] + b0, 0.f), fmaxf(c[3] + b1, 0.f));
            *(uint32_t*)(g_hd + o)          = *(uint32_t*)&h0;
            *(uint32_t*)(g_hd + o + 8 * BN) = *(uint32_t*)&h1;
        }
    }
}

// ------------------------------------------------------------------ kernel 4
// CTA: 64 tokens x 128 out-cols. GRID (8, 512): col chunk fastest so the 8
// CTAs sharing one token tile are co-resident -> shortcut/hd reads hit L2.
static constexpr int G2_ST    = 136;
static constexpr int G2_A     = 64 * G2_ST;
static constexpr int G2_HB    = (64 + 128) * G2_ST;    // halves
static constexpr int G2_OUT   = 64 * 132;              // floats
static constexpr int G2_SMEM  = G2_HB * 2 + (G2_OUT + 128) * 4; // 86528 B

__global__ __launch_bounds__(256, 2) void gemm2(
    const float* __restrict__ bup, float* __restrict__ out)
{
    extern __shared__ __half smC[];
    __half* shd = smC;
    __half* swu = smC + G2_A;
    float*  sout = (float*)(smC + G2_HB);
    float*  sbup = sout + G2_OUT;
    const int tid  = threadIdx.x;
    const int lane = tid & 31, warp = tid >> 5;
    const int nc = blockIdx.x;                 // col chunk (fastest)
    const int t0 = blockIdx.y * 64;            // token tile

    const int mw = warp >> 2, nw = warp & 3;
    const int gid = lane >> 2, tig = lane & 3;

    const int a_row = (lane & 7) + ((lane >> 3) & 1) * 8;
    const int a_kof = (lane >> 4) * 8;
    const int b_row = (lane & 7) + (lane >> 4) * 8;
    const int b_kof = ((lane >> 3) & 1) * 8;

    #pragma unroll
    for (int hk = 0; hk < 2; ++hk) {
        const int k0 = hk * 64;
        #pragma unroll
        for (int p = 0; p < 2; ++p) {           // hd: 64 x 64 halves
            const int idx = p * 256 + tid;
            const int row = idx >> 3, j = (idx & 7) * 8;
            cp16(shd + row * G2_ST + k0 + j, g_hd + (size_t)(t0 + row) * BN + k0 + j);
        }
        #pragma unroll
        for (int p = 0; p < 4; ++p) {           // Wu: 128 x 64 halves
            const int idx = p * 256 + tid;
            const int nn = idx >> 3, j = (idx & 7) * 8;
            cp16(swu + nn * G2_ST + k0 + j,
                 g_Wu + (size_t)(nc * 128 + nn) * BN + k0 + j);
        }
        cp_commit();
    }
    #pragma unroll
    for (int p = 0; p < 8; ++p) {               // shortcut: 64 x 128 floats
        const int idx = p * 256 + tid;
        const int row = idx >> 5, j = (idx & 31) * 4;
        cp16(sout + row * 132 + j, out + (size_t)(t0 + row) * DDIM + nc * 128 + j);
    }
    if (tid < 32) cp16(sbup + tid * 4, bup + nc * 128 + tid * 4);
    cp_commit();

    float acc[2][4][4];
    #pragma unroll
    for (int i = 0; i < 2; ++i)
        #pragma unroll
        for (int j = 0; j < 4; ++j)
            #pragma unroll
            for (int q = 0; q < 4; ++q) acc[i][j][q] = 0.f;

    #pragma unroll
    for (int hk = 0; hk < 2; ++hk) {
        if (hk == 0) cp_wait<2>(); else cp_wait<1>();
        __syncthreads();
        #pragma unroll
        for (int ks = 0; ks < 4; ++ks) {
            const int kb0 = hk * 64 + ks * 16;
            uint32_t a[2][4], bf[2][4];
            #pragma unroll
            for (int mt = 0; mt < 2; ++mt)
                ldsm4(a[mt], shd + (mw * 32 + mt * 16 + a_row) * G2_ST + kb0 + a_kof);
            #pragma unroll
            for (int nt2 = 0; nt2 < 2; ++nt2)
                ldsm4(bf[nt2], swu + (nw * 32 + nt2 * 16 + b_row) * G2_ST + kb0 + b_kof);
            #pragma unroll
            for (int mt = 0; mt < 2; ++mt)
                #pragma unroll
                for (int nt = 0; nt < 4; ++nt)
                    mma16(acc[mt][nt], a[mt], bf[nt >> 1] + (nt & 1) * 2);
        }
    }

    cp_wait<0>();
    __syncthreads();

    #pragma unroll
    for (int mt = 0; mt < 2; ++mt) {
        #pragma unroll
        for (int nt = 0; nt < 4; ++nt) {
            const int row  = mw * 32 + mt * 16 + gid;
            const int col  = nw * 32 + nt * 8 + 2 * tig;
            const int gcol = nc * 128 + col;
            const float b0 = sbup[col], b1 = sbup[col + 1];
            const size_t off  = (size_t)(t0 + row) * DDIM + gcol;
            const size_t off2 = off + (size_t)8 * DDIM;
            const float* c = acc[mt][nt];
            const float2 s0 = *(const float2*)(sout + row * 132 + col);
            const float2 s1 = *(const float2*)(sout + (row + 8) * 132 + col);
            float2 o0, o1;
            o0.x = c[0] + b0 + s0.x; o0.y = c[1] + b1 + s0.y;
            o1.x = c[2] + b0 + s1.x; o1.y = c[3] + b1 + s1.y;
            *(float2*)(out + off)  = o0;
            *(float2*)(out + off2) = o1;
        }
    }
}

// ------------------------------------------------------------------ launch
extern "C" void kernel_launch(void* const* d_in, const int* in_sizes, int n_in,
                              void* d_out, int out_size) {
    const float* x     = (const float*)d_in[0];
    const float* res   = (const float*)d_in[1];
    const float* gamma = (const float*)d_in[2];
    const float* beta  = (const float*)d_in[3];
    const float* Wd    = (const float*)d_in[4];
    const float* bd    = (const float*)d_in[5];
    const float* Wu    = (const float*)d_in[6];
    const float* bup   = (const float*)d_in[7];
    float* out = (float*)d_out;

    static bool attr_done = false;
    if (!attr_done) {
        cudaFuncSetAttribute(gemm1, cudaFuncAttributeMaxDynamicSharedMemorySize, G1_SMEM);
        cudaFuncSetAttribute(gemm2, cudaFuncAttributeMaxDynamicSharedMemorySize, G2_SMEM);
        attr_done = true;
    }

    convert_w<<<128, 256>>>(Wd, Wu);
    resid_ln<<<4096, 256>>>(x, res, gamma, beta, out);
    gemm1<<<512, 256, G1_SMEM>>>(bd);
    gemm2<<<dim3(8, 512), 256, G2_SMEM>>>(bup, out);
}